// round 8
// baseline (speedup 1.0000x reference)
#include <cuda_runtime.h>
#include <cstdint>

#define Tn 4000
#define Bn 16
#define Cn 256
#define G4 1024        // 4*C
#define Mn (Tn*Bn)     // 64000
#define NLAYER 12

// ---------------- scratch (device globals: allocation-free) ----------------
__device__ float g_Xa[(size_t)Mn * Cn];
__device__ float g_Xb[(size_t)Mn * Cn];
__device__ float g_GX[(size_t)Mn * G4];
__device__ float g_bias[NLAYER * G4];

// ---------------- packed f32x2 helpers ----------------
__device__ __forceinline__ void ffma2(unsigned long long& d, unsigned long long a, unsigned long long b) {
    asm("fma.rn.f32x2 %0, %1, %2, %0;" : "+l"(d) : "l"(a), "l"(b));
}
__device__ __forceinline__ unsigned long long pk(float a, float b) {
    unsigned long long r; asm("mov.b64 %0, {%1,%2};" : "=l"(r) : "f"(a), "f"(b)); return r;
}
__device__ __forceinline__ float2 unpk(unsigned long long v) {
    float2 r; asm("mov.b64 {%0,%1}, %2;" : "=f"(r.x), "=f"(r.y) : "l"(v)); return r;
}
__device__ __forceinline__ unsigned long long pku(unsigned lo, unsigned hi) {
    unsigned long long r; asm("mov.b64 %0, {%1,%2};" : "=l"(r) : "r"(lo), "r"(hi)); return r;
}

__device__ __forceinline__ float sig_f(float x) {
    return __fdividef(1.f, 1.f + __expf(-x));
}
__device__ __forceinline__ float tanh_f(float x) {
    float z = __expf(-2.f * fabsf(x));
    float t = __fdividef(1.f - z, 1.f + z);
    return (x < 0.f) ? -t : t;
}

// ---------------- cluster primitives ----------------
// single 8-byte store into peer CTA's smem: data+tag in one word, atomic.
__device__ __forceinline__ void st_peer64(unsigned laddr, unsigned peer, unsigned long long v) {
    asm volatile(
        "{\n\t.reg .u32 ra;\n\t"
        "mapa.shared::cluster.u32 ra, %0, %1;\n\t"
        "st.shared::cluster.u64 [ra], %2;\n\t}"
        :: "r"(laddr), "r"(peer), "l"(v) : "memory");
}
__device__ __forceinline__ unsigned ld_tag_vol(unsigned laddr) {
    unsigned v;
    asm volatile("ld.volatile.shared.u32 %0, [%1];" : "=r"(v) : "r"(laddr) : "memory");
    return v;
}
#define CLUSTER_SYNC() do { \
    asm volatile("barrier.cluster.arrive.aligned;" ::: "memory"); \
    asm volatile("barrier.cluster.wait.aligned;" ::: "memory"); } while (0)

// ---------------- tiny bias precompute ----------------
__global__ void bias_kernel(const float* __restrict__ bih, const float* __restrict__ bhh,
                            float* __restrict__ out) {
    int i = blockIdx.x * 256 + threadIdx.x;
    out[i] = bih[i] + bhh[i];
}

// ---------------- transpose in: x(B,C,L) -> X[t][b][c] ----------------
__global__ void tin_kernel(const float* __restrict__ x, float* __restrict__ X) {
    __shared__ float tile[32][33];
    int t0 = blockIdx.x * 32, c0 = blockIdx.y * 32, b = blockIdx.z;
    int tx = threadIdx.x, ty = threadIdx.y;
    #pragma unroll
    for (int i = 0; i < 32; i += 8)
        tile[ty + i][tx] = x[(size_t)b * Cn * Tn + (size_t)(c0 + ty + i) * Tn + t0 + tx];
    __syncthreads();
    #pragma unroll
    for (int i = 0; i < 32; i += 8)
        X[(size_t)(t0 + ty + i) * Bn * Cn + b * Cn + c0 + tx] = tile[tx][ty + i];
}

// ---------------- transpose out: X[t][b][c] -> out(B,C,L) ----------------
__global__ void tout_kernel(const float* __restrict__ X, float* __restrict__ out) {
    __shared__ float tile[32][33];
    int t0 = blockIdx.x * 32, c0 = blockIdx.y * 32, b = blockIdx.z;
    int tx = threadIdx.x, ty = threadIdx.y;
    #pragma unroll
    for (int i = 0; i < 32; i += 8)
        tile[ty + i][tx] = X[(size_t)(t0 + ty + i) * Bn * Cn + b * Cn + c0 + tx];
    __syncthreads();
    #pragma unroll
    for (int i = 0; i < 32; i += 8)
        out[(size_t)b * Cn * Tn + (size_t)(c0 + ty + i) * Tn + t0 + tx] = tile[tx][ty + i];
}

// ---------------- gx GEMM: GX[m][n] = X[m][k]*W[n][k] + bias[n] ----------------
__global__ __launch_bounds__(256, 2) void gemm_gx(
    const float* __restrict__ X, const float* __restrict__ W,
    const float* __restrict__ bsum, float* __restrict__ GXo)
{
    __shared__ __align__(16) float As[2][8][128];
    __shared__ __align__(16) float Bs[2][8][128];
    const int m0 = blockIdx.y * 128;
    const int n0 = blockIdx.x * 128;
    const int tid = threadIdx.x;
    const int tx = tid & 15, ty = tid >> 4;
    const int lr = tid >> 1;           // 0..127
    const int lk = (tid & 1) * 4;      // 0 or 4

    const float* Ag = X + (size_t)(m0 + lr) * 256 + lk;
    const float* Bg = W + (size_t)(n0 + lr) * 256 + lk;

    auto load_stage = [&](int s, int kc) {
        float4 av = *reinterpret_cast<const float4*>(Ag + kc * 8);
        float4 bv = *reinterpret_cast<const float4*>(Bg + kc * 8);
        As[s][lk + 0][lr] = av.x; As[s][lk + 1][lr] = av.y;
        As[s][lk + 2][lr] = av.z; As[s][lk + 3][lr] = av.w;
        Bs[s][lk + 0][lr] = bv.x; Bs[s][lk + 1][lr] = bv.y;
        Bs[s][lk + 2][lr] = bv.z; Bs[s][lk + 3][lr] = bv.w;
    };

    unsigned long long acc[8][4];
    #pragma unroll
    for (int i = 0; i < 8; i++)
        #pragma unroll
        for (int j = 0; j < 4; j++) acc[i][j] = 0ull;

    load_stage(0, 0);
    __syncthreads();

    for (int kc = 0; kc < 32; ++kc) {
        int s = kc & 1;
        if (kc < 31) load_stage(s ^ 1, kc + 1);
        #pragma unroll
        for (int k = 0; k < 8; k++) {
            float4 a0 = *reinterpret_cast<const float4*>(&As[s][k][ty * 8]);
            float4 a1 = *reinterpret_cast<const float4*>(&As[s][k][ty * 8 + 4]);
            float4 b0 = *reinterpret_cast<const float4*>(&Bs[s][k][tx * 8]);
            float4 b1 = *reinterpret_cast<const float4*>(&Bs[s][k][tx * 8 + 4]);
            unsigned long long bb0 = pk(b0.x, b0.y), bb1 = pk(b0.z, b0.w);
            unsigned long long bb2 = pk(b1.x, b1.y), bb3 = pk(b1.z, b1.w);
            float av[8] = {a0.x, a0.y, a0.z, a0.w, a1.x, a1.y, a1.z, a1.w};
            #pragma unroll
            for (int i = 0; i < 8; i++) {
                unsigned long long aa = pk(av[i], av[i]);
                ffma2(acc[i][0], aa, bb0);
                ffma2(acc[i][1], aa, bb1);
                ffma2(acc[i][2], aa, bb2);
                ffma2(acc[i][3], aa, bb3);
            }
        }
        __syncthreads();
    }

    float bias[8];
    #pragma unroll
    for (int j = 0; j < 8; j++) bias[j] = __ldg(&bsum[n0 + tx * 8 + j]);
    #pragma unroll
    for (int i = 0; i < 8; i++) {
        size_t m = (size_t)(m0 + ty * 8 + i);
        float o[8];
        #pragma unroll
        for (int jp = 0; jp < 4; jp++) {
            float2 v = unpk(acc[i][jp]);
            o[2 * jp] = v.x + bias[2 * jp];
            o[2 * jp + 1] = v.y + bias[2 * jp + 1];
        }
        float4* dst = reinterpret_cast<float4*>(&GXo[m * 1024 + n0 + tx * 8]);
        dst[0] = make_float4(o[0], o[1], o[2], o[3]);
        dst[1] = make_float4(o[4], o[5], o[6], o[7]);
    }
}

// ---------------- persistent LSTM scan: tagged-word exchange, zero barriers ----------------
// 16 clusters of 8 CTAs; cluster = one batch. CTA rank owns units
// [rank*32, rank*32+32). Exchange slot = packed u64 (h_bits, step_tag): a
// single st.shared::cluster.u64 is word-atomic, so data+flag arrive together
// and NO ordering primitive is needed. Double-buffered by t&1; a consumer's
// tag-wait at step t transitively proves all CTAs finished step t-1 reads,
// so tag t+1 writes never clobber live data.
// Lane layout: s = lane&3 (gate), unit = warp*4 + ((lane>>2)&3), kh = lane>>4
// (K-half). Fold by shfl.xor 16; gates gathered by 4 intra-warp shfls;
// (c,h) replicated across the unit's 8 lanes; each of those 8 lanes pushes
// to exactly one cluster CTA (incl. self).
__global__ void __cluster_dims__(8, 1, 1) __launch_bounds__(256, 1)
scan_kernel(const float* __restrict__ Xin, const float* __restrict__ GX,
            const float* __restrict__ Whh, float* __restrict__ Xout, int is_even)
{
    unsigned rank;
    asm("mov.u32 %0, %%cluster_ctarank;" : "=r"(rank));
    const int b = blockIdx.x >> 3;                 // 16 clusters -> batch id
    const int tid = threadIdx.x;
    const int warp = tid >> 5, lane = tid & 31;
    const int s = lane & 3;                        // gate (i,f,g,o)
    const int kh = lane >> 4;                      // K-half
    const int unit = warp * 4 + ((lane >> 2) & 3); // 0..31
    const int col = (int)rank * 32 + unit;         // hidden index 0..255
    const int grow = s * 256 + col;                // W_hh row

    // exchange: ex[par][c] = (h_bits, tag) ; 4KB smem
    __shared__ __align__(16) unsigned long long ex[2][256];

    // K-half weights for this lane's gate row: 128 fp32 register-resident
    ulonglong2 w[32];
    const ulonglong2* wp = reinterpret_cast<const ulonglong2*>(Whh + (size_t)grow * 256 + kh * 128);
    #pragma unroll
    for (int i = 0; i < 32; i++) w[i] = wp[i];

    ex[0][tid] = 0ull;   // h=0, tag=0 (step-0 input)
    ex[1][tid] = 0ull;   // kill stale tags from previous launches
    float c_state = 0.f;
    __syncthreads();
    CLUSTER_SYNC();      // all inits visible before any push can land

    const unsigned exb = (unsigned)__cvta_generic_to_shared(&ex[0][0]);
    const unsigned my_slot_off = (unsigned)(col * 8);
    const unsigned pidx = (unsigned)(s | (kh << 2));        // 0..7
    const unsigned dr = (rank + pidx) & 7u;                  // my push target

    const float* gxp = GX + (size_t)b * G4 + grow;
    float gxv = __ldg(gxp);
    auto src_of = [&](int t) { return is_even ? (t % 400) * 10 + (t / 400) : t; };
    const bool writer = (s == 1 && kh == 0);                 // one lane per unit
    float xres = writer ? __ldg(Xin + ((size_t)src_of(0) * Bn + b) * Cn + col) : 0.f;

    for (int t = 0; t < Tn; ++t) {
        const int par = t & 1;

        // prefetch next step's gx/xres first (LDG flight overlaps the poll)
        float gxn = 0.f, xresn = 0.f;
        if (t + 1 < Tn) {
            gxn = __ldg(gxp + (size_t)(t + 1) * (Bn * G4));
            if (writer)
                xresn = __ldg(Xin + ((size_t)src_of(t + 1) * Bn + b) * Cn + col);
        }

        // wait: all 256 slots of buffer[par] tagged t (8 tag words per lane)
        if (t) {
            const unsigned tgt = (unsigned)t;
            const unsigned pa = exb + (unsigned)(par * 2048 + lane * 8 + 4);
            for (;;) {
                unsigned ok = 1u;
                #pragma unroll
                for (int k = 0; k < 8; k++)
                    ok &= (ld_tag_vol(pa + k * 256u) == tgt) ? 1u : 0u;
                if (__all_sync(0xffffffffu, ok)) break;
            }
        }

        // dot over this lane's K-half: 128 h from packed words
        const float4* hp = reinterpret_cast<const float4*>(&ex[par][kh << 7]);
        unsigned long long a0 = 0ull, a1 = 0ull;
        #pragma unroll
        for (int i = 0; i < 32; i++) {
            float4 q0 = hp[2 * i], q1 = hp[2 * i + 1];   // (h,tag,h,tag)
            ffma2(a0, w[i].x, pk(q0.x, q0.z));
            ffma2(a1, w[i].y, pk(q1.x, q1.z));
        }
        float2 f0 = unpk(a0), f1 = unpk(a1);
        float p0 = (f0.x + f0.y) + (f1.x + f1.y);
        p0 += __shfl_xor_sync(0xffffffffu, p0, 16);   // fold K-halves

        float tot = p0 + gxv;
        float act = (s == 2) ? tanh_f(tot) : sig_f(tot);
        gxv = gxn;

        // gather the 4 gates of this unit
        const int base = lane & ~3;
        float iv = __shfl_sync(0xffffffffu, act, base);
        float fv = __shfl_sync(0xffffffffu, act, base | 1);
        float gv = __shfl_sync(0xffffffffu, act, base | 2);
        float ov = __shfl_sync(0xffffffffu, act, base | 3);

        c_state = fv * c_state + iv * gv;             // replicated across 8 lanes
        float hv = ov * tanh_f(c_state);

        if (t + 1 < Tn) {
            // one packed (h, t+1) push per lane to its assigned cluster CTA
            unsigned long long pv = pku(__float_as_uint(hv), (unsigned)(t + 1));
            st_peer64(exb + (unsigned)((par ^ 1) * 2048) + my_slot_off, dr, pv);
        }
        if (writer) {
            const int dst = is_even ? (t % 400) * 10 + (t / 400) : (Tn - 1 - t);
            Xout[((size_t)dst * Bn + b) * Cn + col] = xres + hv;
        }
        xres = xresn;
    }
}

// ---------------- launch ----------------
extern "C" void kernel_launch(void* const* d_in, const int* in_sizes, int n_in,
                              void* d_out, int out_size) {
    const float* x    = (const float*)d_in[0];
    const float* w_ih = (const float*)d_in[1];
    const float* w_hh = (const float*)d_in[2];
    const float* b_ih = (const float*)d_in[3];
    const float* b_hh = (const float*)d_in[4];

    float *Xa, *Xb, *GXp, *Bp;
    cudaGetSymbolAddress((void**)&Xa, g_Xa);
    cudaGetSymbolAddress((void**)&Xb, g_Xb);
    cudaGetSymbolAddress((void**)&GXp, g_GX);
    cudaGetSymbolAddress((void**)&Bp, g_bias);
    float* Xbuf[2] = {Xa, Xb};

    bias_kernel<<<NLAYER * G4 / 256, 256>>>(b_ih, b_hh, Bp);

    dim3 tgrid(Tn / 32, Cn / 32, Bn), tblk(32, 8);
    tin_kernel<<<tgrid, tblk>>>(x, Xbuf[0]);

    int cur = 0;
    for (int l = 0; l < NLAYER; ++l) {
        gemm_gx<<<dim3(G4 / 128, Mn / 128), 256>>>(
            Xbuf[cur], w_ih + (size_t)l * G4 * Cn, Bp + (size_t)l * G4, GXp);
        scan_kernel<<<Bn * 8, 256>>>(
            Xbuf[cur], GXp, w_hh + (size_t)l * G4 * Cn,
            Xbuf[cur ^ 1], (l & 1) == 0 ? 1 : 0);
        cur ^= 1;
    }

    tout_kernel<<<tgrid, tblk>>>(Xbuf[cur], (float*)d_out);
}

// round 9
// speedup vs baseline: 1.1779x; 1.1779x over previous
#include <cuda_runtime.h>
#include <cstdint>

#define Tn 4000
#define Bn 16
#define Cn 256
#define G4 1024        // 4*C
#define Mn (Tn*Bn)     // 64000
#define NLAYER 12

// ---------------- scratch (device globals: allocation-free) ----------------
__device__ float g_Xa[(size_t)Mn * Cn];
__device__ float g_Xb[(size_t)Mn * Cn];
__device__ float g_GX[(size_t)Mn * G4];
__device__ float g_bias[NLAYER * G4];

// ---------------- packed f32x2 helpers ----------------
__device__ __forceinline__ void ffma2(unsigned long long& d, unsigned long long a, unsigned long long b) {
    asm("fma.rn.f32x2 %0, %1, %2, %0;" : "+l"(d) : "l"(a), "l"(b));
}
__device__ __forceinline__ unsigned long long pk(float a, float b) {
    unsigned long long r; asm("mov.b64 %0, {%1,%2};" : "=l"(r) : "f"(a), "f"(b)); return r;
}
__device__ __forceinline__ float2 unpk(unsigned long long v) {
    float2 r; asm("mov.b64 {%0,%1}, %2;" : "=f"(r.x), "=f"(r.y) : "l"(v)); return r;
}

__device__ __forceinline__ float sig_f(float x) {
    return __fdividef(1.f, 1.f + __expf(-x));
}
__device__ __forceinline__ float tanh_f(float x) {
    float z = __expf(-2.f * fabsf(x));
    float t = __fdividef(1.f - z, 1.f + z);
    return (x < 0.f) ? -t : t;
}

// ---------------- cluster primitives ----------------
__device__ __forceinline__ void st_peer(unsigned laddr, unsigned peer, float v) {
    asm volatile(
        "{\n\t.reg .u32 ra;\n\t"
        "mapa.shared::cluster.u32 ra, %0, %1;\n\t"
        "st.shared::cluster.f32 [ra], %2;\n\t}"
        :: "r"(laddr), "r"(peer), "f"(v) : "memory");
}
#define CLUSTER_SYNC() do { \
    asm volatile("barrier.cluster.arrive.aligned;" ::: "memory"); \
    asm volatile("barrier.cluster.wait.aligned;" ::: "memory"); } while (0)

// ---------------- tiny bias precompute ----------------
__global__ void bias_kernel(const float* __restrict__ bih, const float* __restrict__ bhh,
                            float* __restrict__ out) {
    int i = blockIdx.x * 256 + threadIdx.x;
    out[i] = bih[i] + bhh[i];
}

// ---------------- transpose in: x(B,C,L) -> X[t][b][c] ----------------
__global__ void tin_kernel(const float* __restrict__ x, float* __restrict__ X) {
    __shared__ float tile[32][33];
    int t0 = blockIdx.x * 32, c0 = blockIdx.y * 32, b = blockIdx.z;
    int tx = threadIdx.x, ty = threadIdx.y;
    #pragma unroll
    for (int i = 0; i < 32; i += 8)
        tile[ty + i][tx] = x[(size_t)b * Cn * Tn + (size_t)(c0 + ty + i) * Tn + t0 + tx];
    __syncthreads();
    #pragma unroll
    for (int i = 0; i < 32; i += 8)
        X[(size_t)(t0 + ty + i) * Bn * Cn + b * Cn + c0 + tx] = tile[tx][ty + i];
}

// ---------------- transpose out: X[t][b][c] -> out(B,C,L) ----------------
__global__ void tout_kernel(const float* __restrict__ X, float* __restrict__ out) {
    __shared__ float tile[32][33];
    int t0 = blockIdx.x * 32, c0 = blockIdx.y * 32, b = blockIdx.z;
    int tx = threadIdx.x, ty = threadIdx.y;
    #pragma unroll
    for (int i = 0; i < 32; i += 8)
        tile[ty + i][tx] = X[(size_t)(t0 + ty + i) * Bn * Cn + b * Cn + c0 + tx];
    __syncthreads();
    #pragma unroll
    for (int i = 0; i < 32; i += 8)
        out[(size_t)b * Cn * Tn + (size_t)(c0 + ty + i) * Tn + t0 + tx] = tile[tx][ty + i];
}

// ---------------- gx GEMM: GX[m][n] = X[m][k]*W[n][k] + bias[n] ----------------
__global__ __launch_bounds__(256, 2) void gemm_gx(
    const float* __restrict__ X, const float* __restrict__ W,
    const float* __restrict__ bsum, float* __restrict__ GXo)
{
    __shared__ __align__(16) float As[2][8][128];
    __shared__ __align__(16) float Bs[2][8][128];
    const int m0 = blockIdx.y * 128;
    const int n0 = blockIdx.x * 128;
    const int tid = threadIdx.x;
    const int tx = tid & 15, ty = tid >> 4;
    const int lr = tid >> 1;           // 0..127
    const int lk = (tid & 1) * 4;      // 0 or 4

    const float* Ag = X + (size_t)(m0 + lr) * 256 + lk;
    const float* Bg = W + (size_t)(n0 + lr) * 256 + lk;

    auto load_stage = [&](int s, int kc) {
        float4 av = *reinterpret_cast<const float4*>(Ag + kc * 8);
        float4 bv = *reinterpret_cast<const float4*>(Bg + kc * 8);
        As[s][lk + 0][lr] = av.x; As[s][lk + 1][lr] = av.y;
        As[s][lk + 2][lr] = av.z; As[s][lk + 3][lr] = av.w;
        Bs[s][lk + 0][lr] = bv.x; Bs[s][lk + 1][lr] = bv.y;
        Bs[s][lk + 2][lr] = bv.z; Bs[s][lk + 3][lr] = bv.w;
    };

    unsigned long long acc[8][4];
    #pragma unroll
    for (int i = 0; i < 8; i++)
        #pragma unroll
        for (int j = 0; j < 4; j++) acc[i][j] = 0ull;

    load_stage(0, 0);
    __syncthreads();

    for (int kc = 0; kc < 32; ++kc) {
        int s = kc & 1;
        if (kc < 31) load_stage(s ^ 1, kc + 1);
        #pragma unroll
        for (int k = 0; k < 8; k++) {
            float4 a0 = *reinterpret_cast<const float4*>(&As[s][k][ty * 8]);
            float4 a1 = *reinterpret_cast<const float4*>(&As[s][k][ty * 8 + 4]);
            float4 b0 = *reinterpret_cast<const float4*>(&Bs[s][k][tx * 8]);
            float4 b1 = *reinterpret_cast<const float4*>(&Bs[s][k][tx * 8 + 4]);
            unsigned long long bb0 = pk(b0.x, b0.y), bb1 = pk(b0.z, b0.w);
            unsigned long long bb2 = pk(b1.x, b1.y), bb3 = pk(b1.z, b1.w);
            float av[8] = {a0.x, a0.y, a0.z, a0.w, a1.x, a1.y, a1.z, a1.w};
            #pragma unroll
            for (int i = 0; i < 8; i++) {
                unsigned long long aa = pk(av[i], av[i]);
                ffma2(acc[i][0], aa, bb0);
                ffma2(acc[i][1], aa, bb1);
                ffma2(acc[i][2], aa, bb2);
                ffma2(acc[i][3], aa, bb3);
            }
        }
        __syncthreads();
    }

    float bias[8];
    #pragma unroll
    for (int j = 0; j < 8; j++) bias[j] = __ldg(&bsum[n0 + tx * 8 + j]);
    #pragma unroll
    for (int i = 0; i < 8; i++) {
        size_t m = (size_t)(m0 + ty * 8 + i);
        float o[8];
        #pragma unroll
        for (int jp = 0; jp < 4; jp++) {
            float2 v = unpk(acc[i][jp]);
            o[2 * jp] = v.x + bias[2 * jp];
            o[2 * jp + 1] = v.y + bias[2 * jp + 1];
        }
        float4* dst = reinterpret_cast<float4*>(&GXo[m * 1024 + n0 + tx * 8]);
        dst[0] = make_float4(o[0], o[1], o[2], o[3]);
        dst[1] = make_float4(o[4], o[5], o[6], o[7]);
    }
}

// ---------------- persistent LSTM scan: NBPC=1, gate-per-lane ----------------
// 16 clusters of 8 CTAs; cluster = one batch element. CTA rank owns units
// [rank*32, rank*32+32). Lane layout per warp: s = lane&3 (gate i,f,g,o),
// unit = warp*4 + ((lane>>2)&3), kh = lane>>4 (K-half). Per step:
//   K-half dot (64 FFMA2 + 16 LDS.128) -> shfl.xor(16) fold (both halves get
//   the full 256-dot) -> per-lane gate activation -> 4-shfl gate gather ->
//   (c,h) update replicated across the unit's 8 lanes -> each lane pushes hv
//   to exactly ONE cluster CTA (pidx = s|(kh<<2), incl. self) -> ONE
//   barrier.cluster. No __syncthreads, no smem act round-trip.
__global__ void __cluster_dims__(8, 1, 1) __launch_bounds__(256, 1)
scan_kernel(const float* __restrict__ Xin, const float* __restrict__ GX,
            const float* __restrict__ Whh, float* __restrict__ Xout, int is_even)
{
    unsigned rank;
    asm("mov.u32 %0, %%cluster_ctarank;" : "=r"(rank));
    const int b = blockIdx.x >> 3;                 // 16 clusters -> batch id
    const int tid = threadIdx.x;
    const int warp = tid >> 5, lane = tid & 31;
    const int s = lane & 3;                        // gate
    const int kh = lane >> 4;                      // K-half
    const int unit = warp * 4 + ((lane >> 2) & 3); // 0..31
    const int col = (int)rank * 32 + unit;         // hidden index
    const int grow = s * 256 + col;                // W_hh row

    __shared__ __align__(16) float h_s[2][256];

    // K-half weights for this lane's gate row: 128 fp32 register-resident
    ulonglong2 w[32];
    const ulonglong2* wp = reinterpret_cast<const ulonglong2*>(Whh + (size_t)grow * 256 + kh * 128);
    #pragma unroll
    for (int i = 0; i < 32; i++) w[i] = wp[i];

    h_s[0][tid] = 0.f;
    float c_state = 0.f;
    __syncthreads();
    CLUSTER_SYNC();

    const float* gxp = GX + (size_t)b * G4 + grow;
    float gxv = __ldg(gxp);
    auto src_of = [&](int t) { return is_even ? (t % 400) * 10 + (t / 400) : t; };
    const bool writer = (s == 1 && kh == 0);       // one lane per unit
    float xres = writer ? __ldg(Xin + ((size_t)src_of(0) * Bn + b) * Cn + col) : 0.f;

    const unsigned pidx = (unsigned)(s | (kh << 2));     // 0..7
    const unsigned dr = (rank + pidx) & 7u;               // my push target

    for (int t = 0; t < Tn; ++t) {
        const int par = t & 1;

        // prefetch next step's gx/xres (consumed after the next barrier)
        float gxn = 0.f, xresn = 0.f;
        if (t + 1 < Tn) {
            gxn = __ldg(gxp + (size_t)(t + 1) * (Bn * G4));
            if (writer)
                xresn = __ldg(Xin + ((size_t)src_of(t + 1) * Bn + b) * Cn + col);
        }

        // dot over this lane's K-half: 128 MACs via FFMA2, 4 accumulators
        const ulonglong2* h2 = reinterpret_cast<const ulonglong2*>(&h_s[par][kh << 7]);
        unsigned long long a0 = 0ull, a1 = 0ull, a2 = 0ull, a3 = 0ull;
        #pragma unroll
        for (int i = 0; i < 32; i += 2) {
            ulonglong2 x0 = h2[i], x1 = h2[i + 1];
            ffma2(a0, w[i].x,     x0.x); ffma2(a1, w[i].y,     x0.y);
            ffma2(a2, w[i + 1].x, x1.x); ffma2(a3, w[i + 1].y, x1.y);
        }
        float2 f0 = unpk(a0), f1 = unpk(a1), f2 = unpk(a2), f3 = unpk(a3);
        float p = ((f0.x + f0.y) + (f1.x + f1.y)) + ((f2.x + f2.y) + (f3.x + f3.y));
        p += __shfl_xor_sync(0xffffffffu, p, 16);   // fold K-halves -> full dot

        float tot = p + gxv;
        float act = (s == 2) ? tanh_f(tot) : sig_f(tot);
        gxv = gxn;

        // gather the 4 gates of this unit (within same kh group)
        const int base = lane & ~3;
        float iv = __shfl_sync(0xffffffffu, act, base);
        float fv = __shfl_sync(0xffffffffu, act, base | 1);
        float gv = __shfl_sync(0xffffffffu, act, base | 2);
        float ov = __shfl_sync(0xffffffffu, act, base | 3);

        c_state = fv * c_state + iv * gv;            // replicated across 8 lanes
        float hv = ov * tanh_f(c_state);

        if (t + 1 < Tn) {
            // one 4B push per lane to its assigned cluster CTA (incl. self)
            unsigned laddr = (unsigned)__cvta_generic_to_shared(&h_s[par ^ 1][col]);
            st_peer(laddr, dr, hv);
        }
        if (writer) {
            const int dst = is_even ? (t % 400) * 10 + (t / 400) : (Tn - 1 - t);
            Xout[((size_t)dst * Bn + b) * Cn + col] = xres + hv;
        }
        xres = xresn;

        CLUSTER_SYNC();   // publishes all DSMEM pushes for step t+1
    }
}

// ---------------- launch ----------------
extern "C" void kernel_launch(void* const* d_in, const int* in_sizes, int n_in,
                              void* d_out, int out_size) {
    const float* x    = (const float*)d_in[0];
    const float* w_ih = (const float*)d_in[1];
    const float* w_hh = (const float*)d_in[2];
    const float* b_ih = (const float*)d_in[3];
    const float* b_hh = (const float*)d_in[4];

    float *Xa, *Xb, *GXp, *Bp;
    cudaGetSymbolAddress((void**)&Xa, g_Xa);
    cudaGetSymbolAddress((void**)&Xb, g_Xb);
    cudaGetSymbolAddress((void**)&GXp, g_GX);
    cudaGetSymbolAddress((void**)&Bp, g_bias);
    float* Xbuf[2] = {Xa, Xb};

    bias_kernel<<<NLAYER * G4 / 256, 256>>>(b_ih, b_hh, Bp);

    dim3 tgrid(Tn / 32, Cn / 32, Bn), tblk(32, 8);
    tin_kernel<<<tgrid, tblk>>>(x, Xbuf[0]);

    int cur = 0;
    for (int l = 0; l < NLAYER; ++l) {
        gemm_gx<<<dim3(G4 / 128, Mn / 128), 256>>>(
            Xbuf[cur], w_ih + (size_t)l * G4 * Cn, Bp + (size_t)l * G4, GXp);
        scan_kernel<<<Bn * 8, 256>>>(
            Xbuf[cur], GXp, w_hh + (size_t)l * G4 * Cn,
            Xbuf[cur ^ 1], (l & 1) == 0 ? 1 : 0);
        cur ^= 1;
    }

    tout_kernel<<<tgrid, tblk>>>(Xbuf[cur], (float*)d_out);
}

// round 10
// speedup vs baseline: 1.6103x; 1.3671x over previous
#include <cuda_runtime.h>
#include <cstdint>

#define Tn 4000
#define Bn 16
#define Cn 256
#define G4 1024        // 4*C
#define Mn (Tn*Bn)     // 64000
#define NLAYER 12
#define NBPC 2         // batches per cluster
#define NCLUSTER (Bn / NBPC)   // 8 clusters of 8 CTAs = 64 CTAs (<112 limit!)

// ---------------- scratch (device globals: allocation-free) ----------------
__device__ float g_Xa[(size_t)Mn * Cn];
__device__ float g_Xb[(size_t)Mn * Cn];
__device__ float g_GX[(size_t)Mn * G4];
__device__ float g_bias[NLAYER * G4];

// ---------------- packed f32x2 helpers ----------------
__device__ __forceinline__ void ffma2(unsigned long long& d, unsigned long long a, unsigned long long b) {
    asm("fma.rn.f32x2 %0, %1, %2, %0;" : "+l"(d) : "l"(a), "l"(b));
}
__device__ __forceinline__ unsigned long long pk(float a, float b) {
    unsigned long long r; asm("mov.b64 %0, {%1,%2};" : "=l"(r) : "f"(a), "f"(b)); return r;
}
__device__ __forceinline__ float2 unpk(unsigned long long v) {
    float2 r; asm("mov.b64 {%0,%1}, %2;" : "=f"(r.x), "=f"(r.y) : "l"(v)); return r;
}

// MUFU.TANH — HW tanh, ~1e-5 error, replaces exp+div chains
__device__ __forceinline__ float tanh_mufu(float x) {
    float r; asm("tanh.approx.f32 %0, %1;" : "=f"(r) : "f"(x)); return r;
}
__device__ __forceinline__ float sig_mufu(float x) {
    return fmaf(0.5f, tanh_mufu(0.5f * x), 0.5f);
}

// ---------------- cluster primitives ----------------
__device__ __forceinline__ void st_peer(unsigned laddr, unsigned peer, float v) {
    asm volatile(
        "{\n\t.reg .u32 ra;\n\t"
        "mapa.shared::cluster.u32 ra, %0, %1;\n\t"
        "st.shared::cluster.f32 [ra], %2;\n\t}"
        :: "r"(laddr), "r"(peer), "f"(v) : "memory");
}
// release-store tag to a peer CTA's smem: orders THIS thread's prior cluster
// stores (the data pushes) before the tag, at cluster scope.
__device__ __forceinline__ void st_tag_rel(unsigned laddr, unsigned peer, unsigned v) {
    asm volatile(
        "{\n\t.reg .u32 ra;\n\t"
        "mapa.shared::cluster.u32 ra, %0, %1;\n\t"
        "st.release.cluster.shared::cluster.u32 [ra], %2;\n\t}"
        :: "r"(laddr), "r"(peer), "r"(v) : "memory");
}
__device__ __forceinline__ unsigned ld_tag_acq(unsigned laddr) {
    unsigned v;
    asm volatile("ld.acquire.cluster.shared::cta.u32 %0, [%1];"
                 : "=r"(v) : "r"(laddr) : "memory");
    return v;
}
#define CLUSTER_SYNC() do { \
    asm volatile("barrier.cluster.arrive.aligned;" ::: "memory"); \
    asm volatile("barrier.cluster.wait.aligned;" ::: "memory"); } while (0)

// ---------------- tiny bias precompute ----------------
__global__ void bias_kernel(const float* __restrict__ bih, const float* __restrict__ bhh,
                            float* __restrict__ out) {
    int i = blockIdx.x * 256 + threadIdx.x;
    out[i] = bih[i] + bhh[i];
}

// ---------------- transpose in: x(B,C,L) -> X[t][b][c] ----------------
__global__ void tin_kernel(const float* __restrict__ x, float* __restrict__ X) {
    __shared__ float tile[32][33];
    int t0 = blockIdx.x * 32, c0 = blockIdx.y * 32, b = blockIdx.z;
    int tx = threadIdx.x, ty = threadIdx.y;
    #pragma unroll
    for (int i = 0; i < 32; i += 8)
        tile[ty + i][tx] = x[(size_t)b * Cn * Tn + (size_t)(c0 + ty + i) * Tn + t0 + tx];
    __syncthreads();
    #pragma unroll
    for (int i = 0; i < 32; i += 8)
        X[(size_t)(t0 + ty + i) * Bn * Cn + b * Cn + c0 + tx] = tile[tx][ty + i];
}

// ---------------- transpose out: X[t][b][c] -> out(B,C,L) ----------------
__global__ void tout_kernel(const float* __restrict__ X, float* __restrict__ out) {
    __shared__ float tile[32][33];
    int t0 = blockIdx.x * 32, c0 = blockIdx.y * 32, b = blockIdx.z;
    int tx = threadIdx.x, ty = threadIdx.y;
    #pragma unroll
    for (int i = 0; i < 32; i += 8)
        tile[ty + i][tx] = X[(size_t)(t0 + ty + i) * Bn * Cn + b * Cn + c0 + tx];
    __syncthreads();
    #pragma unroll
    for (int i = 0; i < 32; i += 8)
        out[(size_t)b * Cn * Tn + (size_t)(c0 + ty + i) * Tn + t0 + tx] = tile[tx][ty + i];
}

// ---------------- gx GEMM: GX[m][n] = X[m][k]*W[n][k] + bias[n] ----------------
__global__ __launch_bounds__(256, 2) void gemm_gx(
    const float* __restrict__ X, const float* __restrict__ W,
    const float* __restrict__ bsum, float* __restrict__ GXo)
{
    __shared__ __align__(16) float As[2][8][128];
    __shared__ __align__(16) float Bs[2][8][128];
    const int m0 = blockIdx.y * 128;
    const int n0 = blockIdx.x * 128;
    const int tid = threadIdx.x;
    const int tx = tid & 15, ty = tid >> 4;
    const int lr = tid >> 1;           // 0..127
    const int lk = (tid & 1) * 4;      // 0 or 4

    const float* Ag = X + (size_t)(m0 + lr) * 256 + lk;
    const float* Bg = W + (size_t)(n0 + lr) * 256 + lk;

    auto load_stage = [&](int s, int kc) {
        float4 av = *reinterpret_cast<const float4*>(Ag + kc * 8);
        float4 bv = *reinterpret_cast<const float4*>(Bg + kc * 8);
        As[s][lk + 0][lr] = av.x; As[s][lk + 1][lr] = av.y;
        As[s][lk + 2][lr] = av.z; As[s][lk + 3][lr] = av.w;
        Bs[s][lk + 0][lr] = bv.x; Bs[s][lk + 1][lr] = bv.y;
        Bs[s][lk + 2][lr] = bv.z; Bs[s][lk + 3][lr] = bv.w;
    };

    unsigned long long acc[8][4];
    #pragma unroll
    for (int i = 0; i < 8; i++)
        #pragma unroll
        for (int j = 0; j < 4; j++) acc[i][j] = 0ull;

    load_stage(0, 0);
    __syncthreads();

    for (int kc = 0; kc < 32; ++kc) {
        int s = kc & 1;
        if (kc < 31) load_stage(s ^ 1, kc + 1);
        #pragma unroll
        for (int k = 0; k < 8; k++) {
            float4 a0 = *reinterpret_cast<const float4*>(&As[s][k][ty * 8]);
            float4 a1 = *reinterpret_cast<const float4*>(&As[s][k][ty * 8 + 4]);
            float4 b0 = *reinterpret_cast<const float4*>(&Bs[s][k][tx * 8]);
            float4 b1 = *reinterpret_cast<const float4*>(&Bs[s][k][tx * 8 + 4]);
            unsigned long long bb0 = pk(b0.x, b0.y), bb1 = pk(b0.z, b0.w);
            unsigned long long bb2 = pk(b1.x, b1.y), bb3 = pk(b1.z, b1.w);
            float av[8] = {a0.x, a0.y, a0.z, a0.w, a1.x, a1.y, a1.z, a1.w};
            #pragma unroll
            for (int i = 0; i < 8; i++) {
                unsigned long long aa = pk(av[i], av[i]);
                ffma2(acc[i][0], aa, bb0);
                ffma2(acc[i][1], aa, bb1);
                ffma2(acc[i][2], aa, bb2);
                ffma2(acc[i][3], aa, bb3);
            }
        }
        __syncthreads();
    }

    float bias[8];
    #pragma unroll
    for (int j = 0; j < 8; j++) bias[j] = __ldg(&bsum[n0 + tx * 8 + j]);
    #pragma unroll
    for (int i = 0; i < 8; i++) {
        size_t m = (size_t)(m0 + ty * 8 + i);
        float o[8];
        #pragma unroll
        for (int jp = 0; jp < 4; jp++) {
            float2 v = unpk(acc[i][jp]);
            o[2 * jp] = v.x + bias[2 * jp];
            o[2 * jp + 1] = v.y + bias[2 * jp + 1];
        }
        float4* dst = reinterpret_cast<float4*>(&GXo[m * 1024 + n0 + tx * 8]);
        dst[0] = make_float4(o[0], o[1], o[2], o[3]);
        dst[1] = make_float4(o[4], o[5], o[6], o[7]);
    }
}

// ---------------- persistent LSTM scan: released tags + single-warp poll ----------------
// 8 clusters of 8 CTAs (64 CTAs < 112 cluster-CTA limit); cluster cl advances
// batches {2cl, 2cl+1}. Lane layout (R7): s = lane&3 (gate), kh = lane>>4
// (K-half AND batch), unit = warp*4 + ((lane>>2)&3), col = rank*32+unit.
// Dot computes both batches over the lane's K-half; shfl.xor(16) folds halves.
// Exchange: each lane pushes its (col, batch=kh) h to dests (rank+s)&7 and
// (rank+s+4)&7 via plain DSMEM store, then release-stores tag=t+1 to the same
// per-slot tag word (one writer per tag, no contention). Consumer: warp 0
// acquire-polls the 512 tags of the current buffer, warps 1-7 sleep in
// __syncthreads. No cluster barrier in the loop -> wavefront skew absorption.
__global__ void __cluster_dims__(8, 1, 1) __launch_bounds__(256, 1)
scan_kernel(const float* __restrict__ Xin, const float* __restrict__ GX,
            const float* __restrict__ Whh, float* __restrict__ Xout, int is_even)
{
    unsigned rank;
    asm("mov.u32 %0, %%cluster_ctarank;" : "=r"(rank));
    const int cl = blockIdx.x >> 3;
    const int b0 = cl * NBPC;
    const int tid = threadIdx.x;
    const int warp = tid >> 5, lane = tid & 31;
    const int s = lane & 3;                        // gate (i,f,g,o)
    const int kh = lane >> 4;                      // K-half = batch index
    const int unit = warp * 4 + ((lane >> 2) & 3); // 0..31
    const int col = (int)rank * 32 + unit;         // hidden index 0..255
    const int grow = s * 256 + col;                // W_hh row
    const int bsel = b0 + kh;

    __shared__ __align__(16) float h_s[2][NBPC][256];   // 4KB
    __shared__ __align__(16) unsigned tg_s[2][512];     // 4KB  [par][kh*256+col]

    // K-half weights for this lane's gate row: 128 fp32 register-resident
    ulonglong2 w[32];
    const ulonglong2* wp = reinterpret_cast<const ulonglong2*>(Whh + (size_t)grow * 256 + kh * 128);
    #pragma unroll
    for (int i = 0; i < 32; i++) w[i] = wp[i];

    h_s[0][0][tid] = 0.f;
    h_s[0][1][tid] = 0.f;
    tg_s[0][tid] = 0u; tg_s[0][256 + tid] = 0u;
    tg_s[1][tid] = 0u; tg_s[1][256 + tid] = 0u;
    float c_state = 0.f;
    __syncthreads();
    CLUSTER_SYNC();   // inits visible cluster-wide before any push can land

    const unsigned hsb = (unsigned)__cvta_generic_to_shared(&h_s[0][0][0]);
    const unsigned tgb = (unsigned)__cvta_generic_to_shared(&tg_s[0][0]);
    const unsigned slot = (unsigned)(kh * 256 + col);          // 0..511
    const unsigned d1 = (rank + (unsigned)s) & 7u;             // incl self at s==0
    const unsigned d2 = (rank + (unsigned)s + 4u) & 7u;

    const float* gxp = GX + (size_t)bsel * G4 + grow;
    float gxv = __ldg(gxp);
    auto src_of = [&](int t) { return is_even ? (t % 400) * 10 + (t / 400) : t; };
    const bool writer = (s == 1);   // one lane per (unit,batch) writes Xout
    float xres = writer ? __ldg(Xin + ((size_t)src_of(0) * Bn + bsel) * Cn + col) : 0.f;

    for (int t = 0; t < Tn; ++t) {
        const int par = t & 1;

        // prefetch next step's gx/xres (LDG flight overlaps poll + dot)
        float gxn = 0.f, xresn = 0.f;
        if (t + 1 < Tn) {
            gxn = __ldg(gxp + (size_t)(t + 1) * (Bn * G4));
            if (writer)
                xresn = __ldg(Xin + ((size_t)src_of(t + 1) * Bn + bsel) * Cn + col);
        }

        // wait: warp 0 polls the 512 tags of buffer[par] for value t
        if (t) {
            if (warp == 0) {
                const unsigned tgt = (unsigned)t;
                const unsigned ta = tgb + (unsigned)(par * 2048 + lane * 4);
                for (;;) {
                    unsigned ok = 1u;
                    #pragma unroll
                    for (int k = 0; k < 16; k++)
                        ok &= (ld_tag_acq(ta + (unsigned)(k * 128)) == tgt) ? 1u : 0u;
                    if (__all_sync(0xffffffffu, ok)) break;
                }
            }
            __syncthreads();
        }

        // both-batch dot over this lane's K-half (128 FFMA2, 64 LDS.128)
        const ulonglong2* hA = reinterpret_cast<const ulonglong2*>(&h_s[par][0][kh << 7]);
        const ulonglong2* hB = reinterpret_cast<const ulonglong2*>(&h_s[par][1][kh << 7]);
        unsigned long long a00 = 0, a01 = 0, a10 = 0, a11 = 0;
        #pragma unroll
        for (int i = 0; i < 32; i++) {
            ulonglong2 xA = hA[i], xB = hB[i];
            ffma2(a00, w[i].x, xA.x); ffma2(a01, w[i].y, xA.y);
            ffma2(a10, w[i].x, xB.x); ffma2(a11, w[i].y, xB.y);
        }
        float2 f0 = unpk(a00), f1 = unpk(a01);
        float p0 = (f0.x + f0.y) + (f1.x + f1.y);
        float2 f2 = unpk(a10), f3 = unpk(a11);
        float p1 = (f2.x + f2.y) + (f3.x + f3.y);
        p0 += __shfl_xor_sync(0xffffffffu, p0, 16);   // fold K-halves
        p1 += __shfl_xor_sync(0xffffffffu, p1, 16);

        // lane's batch = kh; one gate activation per lane (MUFU.TANH)
        float tot = (kh ? p1 : p0) + gxv;
        float act = (s == 2) ? tanh_mufu(tot) : sig_mufu(tot);
        gxv = gxn;

        // gather this unit's 4 gates (same kh group)
        const int base = lane & ~3;
        float iv = __shfl_sync(0xffffffffu, act, base);
        float fv = __shfl_sync(0xffffffffu, act, base | 1);
        float gv = __shfl_sync(0xffffffffu, act, base | 2);
        float ov = __shfl_sync(0xffffffffu, act, base | 3);

        c_state = fv * c_state + iv * gv;             // replicated across 4 lanes
        float hv = ov * tanh_mufu(c_state);

        if (t + 1 < Tn) {
            const int nb = par ^ 1;
            const unsigned ha = hsb + (unsigned)((nb * 512 + kh * 256 + col) * 4);
            const unsigned ta = tgb + (unsigned)(nb * 2048) + slot * 4u;
            st_peer(ha, d1, hv);                       // data to both dests
            st_peer(ha, d2, hv);
            st_tag_rel(ta, d1, (unsigned)(t + 1));     // release orders data first
            st_tag_rel(ta, d2, (unsigned)(t + 1));
        }
        if (writer) {
            const int dst = is_even ? (t % 400) * 10 + (t / 400) : (Tn - 1 - t);
            Xout[((size_t)dst * Bn + bsel) * Cn + col] = xres + hv;
        }
        xres = xresn;
    }
}

// ---------------- launch ----------------
extern "C" void kernel_launch(void* const* d_in, const int* in_sizes, int n_in,
                              void* d_out, int out_size) {
    const float* x    = (const float*)d_in[0];
    const float* w_ih = (const float*)d_in[1];
    const float* w_hh = (const float*)d_in[2];
    const float* b_ih = (const float*)d_in[3];
    const float* b_hh = (const float*)d_in[4];

    float *Xa, *Xb, *GXp, *Bp;
    cudaGetSymbolAddress((void**)&Xa, g_Xa);
    cudaGetSymbolAddress((void**)&Xb, g_Xb);
    cudaGetSymbolAddress((void**)&GXp, g_GX);
    cudaGetSymbolAddress((void**)&Bp, g_bias);
    float* Xbuf[2] = {Xa, Xb};

    bias_kernel<<<NLAYER * G4 / 256, 256>>>(b_ih, b_hh, Bp);

    dim3 tgrid(Tn / 32, Cn / 32, Bn), tblk(32, 8);
    tin_kernel<<<tgrid, tblk>>>(x, Xbuf[0]);

    int cur = 0;
    for (int l = 0; l < NLAYER; ++l) {
        gemm_gx<<<dim3(G4 / 128, Mn / 128), 256>>>(
            Xbuf[cur], w_ih + (size_t)l * G4 * Cn, Bp + (size_t)l * G4, GXp);
        scan_kernel<<<NCLUSTER * 8, 256>>>(
            Xbuf[cur], GXp, w_hh + (size_t)l * G4 * Cn,
            Xbuf[cur ^ 1], (l & 1) == 0 ? 1 : 0);
        cur ^= 1;
    }

    tout_kernel<<<tgrid, tblk>>>(Xbuf[cur], (float*)d_out);
}

// round 11
// speedup vs baseline: 1.9955x; 1.2392x over previous
#include <cuda_runtime.h>
#include <cstdint>

#define Tn 4000
#define Bn 16
#define Cn 256
#define G4 1024        // 4*C
#define Mn (Tn*Bn)     // 64000
#define NLAYER 12
#define NBPC 2         // batches per cluster
#define NCLUSTER (Bn / NBPC)   // 8 clusters of 8 CTAs = 64 CTAs (< 112 limit)

// ---------------- scratch (device globals: allocation-free) ----------------
__device__ float g_Xa[(size_t)Mn * Cn];
__device__ float g_Xb[(size_t)Mn * Cn];
__device__ float g_GX[(size_t)Mn * G4];
__device__ float g_bias[NLAYER * G4];

// ---------------- packed f32x2 helpers ----------------
__device__ __forceinline__ void ffma2(unsigned long long& d, unsigned long long a, unsigned long long b) {
    asm("fma.rn.f32x2 %0, %1, %2, %0;" : "+l"(d) : "l"(a), "l"(b));
}
__device__ __forceinline__ unsigned long long pk(float a, float b) {
    unsigned long long r; asm("mov.b64 %0, {%1,%2};" : "=l"(r) : "f"(a), "f"(b)); return r;
}
__device__ __forceinline__ float2 unpk(unsigned long long v) {
    float2 r; asm("mov.b64 {%0,%1}, %2;" : "=f"(r.x), "=f"(r.y) : "l"(v)); return r;
}

// MUFU.TANH — single HW op (~1e-5 err), replaces exp+div chains
__device__ __forceinline__ float tanh_mufu(float x) {
    float r; asm("tanh.approx.f32 %0, %1;" : "=f"(r) : "f"(x)); return r;
}
__device__ __forceinline__ float sig_mufu(float x) {
    return fmaf(0.5f, tanh_mufu(0.5f * x), 0.5f);
}

// ---------------- cluster primitives ----------------
__device__ __forceinline__ void st_peer(unsigned laddr, unsigned peer, float v) {
    asm volatile(
        "{\n\t.reg .u32 ra;\n\t"
        "mapa.shared::cluster.u32 ra, %0, %1;\n\t"
        "st.shared::cluster.f32 [ra], %2;\n\t}"
        :: "r"(laddr), "r"(peer), "f"(v) : "memory");
}
#define CLUSTER_ARRIVE() asm volatile("barrier.cluster.arrive.aligned;" ::: "memory")
#define CLUSTER_WAIT()   asm volatile("barrier.cluster.wait.aligned;"   ::: "memory")
#define CLUSTER_SYNC() do { CLUSTER_ARRIVE(); CLUSTER_WAIT(); } while (0)

// ---------------- tiny bias precompute ----------------
__global__ void bias_kernel(const float* __restrict__ bih, const float* __restrict__ bhh,
                            float* __restrict__ out) {
    int i = blockIdx.x * 256 + threadIdx.x;
    out[i] = bih[i] + bhh[i];
}

// ---------------- transpose in: x(B,C,L) -> X[t][b][c] ----------------
__global__ void tin_kernel(const float* __restrict__ x, float* __restrict__ X) {
    __shared__ float tile[32][33];
    int t0 = blockIdx.x * 32, c0 = blockIdx.y * 32, b = blockIdx.z;
    int tx = threadIdx.x, ty = threadIdx.y;
    #pragma unroll
    for (int i = 0; i < 32; i += 8)
        tile[ty + i][tx] = x[(size_t)b * Cn * Tn + (size_t)(c0 + ty + i) * Tn + t0 + tx];
    __syncthreads();
    #pragma unroll
    for (int i = 0; i < 32; i += 8)
        X[(size_t)(t0 + ty + i) * Bn * Cn + b * Cn + c0 + tx] = tile[tx][ty + i];
}

// ---------------- transpose out: X[t][b][c] -> out(B,C,L) ----------------
__global__ void tout_kernel(const float* __restrict__ X, float* __restrict__ out) {
    __shared__ float tile[32][33];
    int t0 = blockIdx.x * 32, c0 = blockIdx.y * 32, b = blockIdx.z;
    int tx = threadIdx.x, ty = threadIdx.y;
    #pragma unroll
    for (int i = 0; i < 32; i += 8)
        tile[ty + i][tx] = X[(size_t)(t0 + ty + i) * Bn * Cn + b * Cn + c0 + tx];
    __syncthreads();
    #pragma unroll
    for (int i = 0; i < 32; i += 8)
        out[(size_t)b * Cn * Tn + (size_t)(c0 + ty + i) * Tn + t0 + tx] = tile[tx][ty + i];
}

// ---------------- gx GEMM: GX[m][n] = X[m][k]*W[n][k] + bias[n] ----------------
__global__ __launch_bounds__(256, 2) void gemm_gx(
    const float* __restrict__ X, const float* __restrict__ W,
    const float* __restrict__ bsum, float* __restrict__ GXo)
{
    __shared__ __align__(16) float As[2][8][128];
    __shared__ __align__(16) float Bs[2][8][128];
    const int m0 = blockIdx.y * 128;
    const int n0 = blockIdx.x * 128;
    const int tid = threadIdx.x;
    const int tx = tid & 15, ty = tid >> 4;
    const int lr = tid >> 1;           // 0..127
    const int lk = (tid & 1) * 4;      // 0 or 4

    const float* Ag = X + (size_t)(m0 + lr) * 256 + lk;
    const float* Bg = W + (size_t)(n0 + lr) * 256 + lk;

    auto load_stage = [&](int s, int kc) {
        float4 av = *reinterpret_cast<const float4*>(Ag + kc * 8);
        float4 bv = *reinterpret_cast<const float4*>(Bg + kc * 8);
        As[s][lk + 0][lr] = av.x; As[s][lk + 1][lr] = av.y;
        As[s][lk + 2][lr] = av.z; As[s][lk + 3][lr] = av.w;
        Bs[s][lk + 0][lr] = bv.x; Bs[s][lk + 1][lr] = bv.y;
        Bs[s][lk + 2][lr] = bv.z; Bs[s][lk + 3][lr] = bv.w;
    };

    unsigned long long acc[8][4];
    #pragma unroll
    for (int i = 0; i < 8; i++)
        #pragma unroll
        for (int j = 0; j < 4; j++) acc[i][j] = 0ull;

    load_stage(0, 0);
    __syncthreads();

    for (int kc = 0; kc < 32; ++kc) {
        int s = kc & 1;
        if (kc < 31) load_stage(s ^ 1, kc + 1);
        #pragma unroll
        for (int k = 0; k < 8; k++) {
            float4 a0 = *reinterpret_cast<const float4*>(&As[s][k][ty * 8]);
            float4 a1 = *reinterpret_cast<const float4*>(&As[s][k][ty * 8 + 4]);
            float4 b0 = *reinterpret_cast<const float4*>(&Bs[s][k][tx * 8]);
            float4 b1 = *reinterpret_cast<const float4*>(&Bs[s][k][tx * 8 + 4]);
            unsigned long long bb0 = pk(b0.x, b0.y), bb1 = pk(b0.z, b0.w);
            unsigned long long bb2 = pk(b1.x, b1.y), bb3 = pk(b1.z, b1.w);
            float av[8] = {a0.x, a0.y, a0.z, a0.w, a1.x, a1.y, a1.z, a1.w};
            #pragma unroll
            for (int i = 0; i < 8; i++) {
                unsigned long long aa = pk(av[i], av[i]);
                ffma2(acc[i][0], aa, bb0);
                ffma2(acc[i][1], aa, bb1);
                ffma2(acc[i][2], aa, bb2);
                ffma2(acc[i][3], aa, bb3);
            }
        }
        __syncthreads();
    }

    float bias[8];
    #pragma unroll
    for (int j = 0; j < 8; j++) bias[j] = __ldg(&bsum[n0 + tx * 8 + j]);
    #pragma unroll
    for (int i = 0; i < 8; i++) {
        size_t m = (size_t)(m0 + ty * 8 + i);
        float o[8];
        #pragma unroll
        for (int jp = 0; jp < 4; jp++) {
            float2 v = unpk(acc[i][jp]);
            o[2 * jp] = v.x + bias[2 * jp];
            o[2 * jp + 1] = v.y + bias[2 * jp + 1];
        }
        float4* dst = reinterpret_cast<float4*>(&GXo[m * 1024 + n0 + tx * 8]);
        dst[0] = make_float4(o[0], o[1], o[2], o[3]);
        dst[1] = make_float4(o[4], o[5], o[6], o[7]);
    }
}

// ---------------- persistent LSTM scan (R7 skeleton + MUFU + split barrier) --
// 8 clusters of 8 CTAs (64 CTAs, single wave); cluster cl advances batches
// {2cl, 2cl+1}. Lane layout: s = lane&3 (gate), kh = lane>>4 (K-half = batch),
// unit = warp*4 + ((lane>>2)&3), col = rank*32+unit. Per step:
//   WAIT (acquire: peers' pushes visible) -> both-batch dot over K-half ->
//   shfl fold -> MUFU gate activation -> 4-shfl gather -> (c,h) update ->
//   push hv to peers -> ARRIVE (release) -> Xout store + next-step prefetch.
// The STG/LDGs issue inside the arrive->wait window, absorbing cluster skew.
__global__ void __cluster_dims__(8, 1, 1) __launch_bounds__(256, 1)
scan_kernel(const float* __restrict__ Xin, const float* __restrict__ GX,
            const float* __restrict__ Whh, float* __restrict__ Xout, int is_even)
{
    unsigned rank;
    asm("mov.u32 %0, %%cluster_ctarank;" : "=r"(rank));
    const int cl = blockIdx.x >> 3;
    const int b0 = cl * NBPC;
    const int tid = threadIdx.x;
    const int warp = tid >> 5, lane = tid & 31;
    const int s = lane & 3;                        // gate (i,f,g,o)
    const int kh = lane >> 4;                      // K-half = batch index
    const int unit = warp * 4 + ((lane >> 2) & 3); // 0..31
    const int col = (int)rank * 32 + unit;         // hidden index 0..255
    const int grow = s * 256 + col;                // W_hh row
    const int bsel = b0 + kh;

    __shared__ __align__(16) float h_s[2][NBPC][256];

    // K-half weights for this lane's gate row: 128 fp32 register-resident
    ulonglong2 w[32];
    const ulonglong2* wp = reinterpret_cast<const ulonglong2*>(Whh + (size_t)grow * 256 + kh * 128);
    #pragma unroll
    for (int i = 0; i < 32; i++) w[i] = wp[i];

    h_s[0][0][tid] = 0.f;
    h_s[0][1][tid] = 0.f;
    float c_state = 0.f;
    __syncthreads();
    CLUSTER_SYNC();

    const float* gxp = GX + (size_t)bsel * G4 + grow;
    float gxv = __ldg(gxp);
    auto src_of = [&](int t) { return is_even ? (t % 400) * 10 + (t / 400) : t; };
    const bool writer = (s == 1);   // one lane per (unit,batch) writes Xout
    float xres = writer ? __ldg(Xin + ((size_t)src_of(0) * Bn + bsel) * Cn + col) : 0.f;

    for (int t = 0; t < Tn; ++t) {
        const int par = t & 1;

        if (t) CLUSTER_WAIT();   // acquire: step-t pushes now visible

        // both-batch dot over this lane's K-half (128 FFMA2, 64 LDS.128)
        const ulonglong2* hA = reinterpret_cast<const ulonglong2*>(&h_s[par][0][kh << 7]);
        const ulonglong2* hB = reinterpret_cast<const ulonglong2*>(&h_s[par][1][kh << 7]);
        unsigned long long a00 = 0, a01 = 0, a10 = 0, a11 = 0;
        #pragma unroll
        for (int i = 0; i < 32; i++) {
            ulonglong2 xA = hA[i], xB = hB[i];
            ffma2(a00, w[i].x, xA.x); ffma2(a01, w[i].y, xA.y);
            ffma2(a10, w[i].x, xB.x); ffma2(a11, w[i].y, xB.y);
        }
        float2 f0 = unpk(a00), f1 = unpk(a01);
        float p0 = (f0.x + f0.y) + (f1.x + f1.y);
        float2 f2 = unpk(a10), f3 = unpk(a11);
        float p1 = (f2.x + f2.y) + (f3.x + f3.y);
        p0 += __shfl_xor_sync(0xffffffffu, p0, 16);   // fold K-halves
        p1 += __shfl_xor_sync(0xffffffffu, p1, 16);

        // lane's batch = kh; one gate activation per lane (MUFU.TANH)
        float tot = (kh ? p1 : p0) + gxv;
        float act = (s == 2) ? tanh_mufu(tot) : sig_mufu(tot);

        // gather this unit's 4 gates (same kh group)
        const int base = lane & ~3;
        float iv = __shfl_sync(0xffffffffu, act, base);
        float fv = __shfl_sync(0xffffffffu, act, base | 1);
        float gv = __shfl_sync(0xffffffffu, act, base | 2);
        float ov = __shfl_sync(0xffffffffu, act, base | 3);

        c_state = fv * c_state + iv * gv;             // replicated across lanes
        float hv = ov * tanh_mufu(c_state);

        const int nb = par ^ 1;
        if (s == 0) h_s[nb][kh][col] = hv;            // local copy
        if (t + 1 < Tn) {
            // lane's gate slot covers peers {s+1, s+5}: all 7 peers covered
            unsigned laddr = (unsigned)__cvta_generic_to_shared(&h_s[nb][kh][col]);
            st_peer(laddr, (rank + (unsigned)s + 1u) & 7u, hv);
            if (s < 3)
                st_peer(laddr, (rank + (unsigned)s + 5u) & 7u, hv);
            CLUSTER_ARRIVE();    // release: orders the pushes above
        }

        // post-arrive work overlaps peers' skew / barrier propagation
        if (writer) {
            const int dst = is_even ? (t % 400) * 10 + (t / 400) : (Tn - 1 - t);
            Xout[((size_t)dst * Bn + bsel) * Cn + col] = xres + hv;
        }
        if (t + 1 < Tn) {
            gxv = __ldg(gxp + (size_t)(t + 1) * (Bn * G4));
            if (writer)
                xres = __ldg(Xin + ((size_t)src_of(t + 1) * Bn + bsel) * Cn + col);
        }
    }
}

// ---------------- launch ----------------
extern "C" void kernel_launch(void* const* d_in, const int* in_sizes, int n_in,
                              void* d_out, int out_size) {
    const float* x    = (const float*)d_in[0];
    const float* w_ih = (const float*)d_in[1];
    const float* w_hh = (const float*)d_in[2];
    const float* b_ih = (const float*)d_in[3];
    const float* b_hh = (const float*)d_in[4];

    float *Xa, *Xb, *GXp, *Bp;
    cudaGetSymbolAddress((void**)&Xa, g_Xa);
    cudaGetSymbolAddress((void**)&Xb, g_Xb);
    cudaGetSymbolAddress((void**)&GXp, g_GX);
    cudaGetSymbolAddress((void**)&Bp, g_bias);
    float* Xbuf[2] = {Xa, Xb};

    bias_kernel<<<NLAYER * G4 / 256, 256>>>(b_ih, b_hh, Bp);

    dim3 tgrid(Tn / 32, Cn / 32, Bn), tblk(32, 8);
    tin_kernel<<<tgrid, tblk>>>(x, Xbuf[0]);

    int cur = 0;
    for (int l = 0; l < NLAYER; ++l) {
        gemm_gx<<<dim3(G4 / 128, Mn / 128), 256>>>(
            Xbuf[cur], w_ih + (size_t)l * G4 * Cn, Bp + (size_t)l * G4, GXp);
        scan_kernel<<<NCLUSTER * 8, 256>>>(
            Xbuf[cur], GXp, w_hh + (size_t)l * G4 * Cn,
            Xbuf[cur ^ 1], (l & 1) == 0 ? 1 : 0);
        cur ^= 1;
    }

    tout_kernel<<<tgrid, tblk>>>(Xbuf[cur], (float*)d_out);
}